// round 2
// baseline (speedup 1.0000x reference)
#include <cuda_runtime.h>
#include <math.h>
#include <stdint.h>

// Problem sizes (fixed by the reference)
#define D   1024
#define DD  (D*D)
#define NB  3
#define BSZ 16384

// ---------------- scratch (device globals; no allocations allowed) ----------
__device__ float g_W [NB*DD];
__device__ float g_X [NB*DD];
__device__ float g_Xb[NB*DD];
__device__ float g_Q [NB*DD];
__device__ float g_Qb[NB*DD];
__device__ float g_Y [NB*DD];
__device__ float g_Y2[NB*DD];
__device__ float g_Z [NB*DD];
__device__ float g_K [NB*DD];
__device__ float g_A1[(size_t)BSZ*D];
__device__ float g_A2[(size_t)BSZ*D];

// ---------------- tiled fp32 matmul: C = op(A)*B (+bias, +act) --------------
// TRA: op(A)=A^T, A stored physically K x M row-major. Otherwise A is M x K.
// B is K x N row-major, C is M x N row-major. batch via blockIdx.z.
// ACT: 0 = plain store, 1 = +bias (identity), 2 = +bias then lipswish.
template<bool TRA, int ACT>
__global__ void __launch_bounds__(256, 2)
mm_kernel(const float* __restrict__ A, const float* __restrict__ B,
          float* __restrict__ C, const float* __restrict__ bias,
          int M, int N, int K)
{
    __shared__ float As[16][128];
    __shared__ float Bs[16][128];

    const int b = blockIdx.z;
    A += (size_t)b * M * K;
    B += (size_t)b * K * N;
    C += (size_t)b * M * N;

    const int m0 = blockIdx.y * 128;
    const int n0 = blockIdx.x * 128;
    const int tid = threadIdx.x;
    const int tm = (tid >> 4) << 3;   // 0..120 step 8
    const int tn = (tid & 15) << 3;   // 0..120 step 8

    float acc[8][8];
#pragma unroll
    for (int i = 0; i < 8; i++)
#pragma unroll
        for (int j = 0; j < 8; j++) acc[i][j] = 0.0f;

    for (int k0 = 0; k0 < K; k0 += 16) {
        if (TRA) {
            // As[kk][mm] = A[(k0+kk)*M + m0+mm]  (contiguous along mm)
#pragma unroll
            for (int i = 0; i < 2; i++) {
                int t  = tid + i * 256;
                int kk = t >> 5;
                int mm = (t & 31) << 2;
                *(float4*)&As[kk][mm] =
                    *(const float4*)(A + (size_t)(k0 + kk) * M + m0 + mm);
            }
        } else {
            // As[kk][mm] = A[(m0+mm)*K + k0+kk]  (load float4 along k, scatter)
#pragma unroll
            for (int i = 0; i < 2; i++) {
                int t  = tid + i * 256;
                int mm = t >> 2;
                int kk = (t & 3) << 2;
                float4 v = *(const float4*)(A + (size_t)(m0 + mm) * K + k0 + kk);
                As[kk + 0][mm] = v.x;
                As[kk + 1][mm] = v.y;
                As[kk + 2][mm] = v.z;
                As[kk + 3][mm] = v.w;
            }
        }
        // Bs[kk][nn] = B[(k0+kk)*N + n0+nn]
#pragma unroll
        for (int i = 0; i < 2; i++) {
            int t  = tid + i * 256;
            int kk = t >> 5;
            int nn = (t & 31) << 2;
            *(float4*)&Bs[kk][nn] =
                *(const float4*)(B + (size_t)(k0 + kk) * N + n0 + nn);
        }
        __syncthreads();

#pragma unroll
        for (int kk = 0; kk < 16; kk++) {
            float a[8], bv[8];
            *(float4*)&a[0]  = *(const float4*)&As[kk][tm];
            *(float4*)&a[4]  = *(const float4*)&As[kk][tm + 4];
            *(float4*)&bv[0] = *(const float4*)&Bs[kk][tn];
            *(float4*)&bv[4] = *(const float4*)&Bs[kk][tn + 4];
#pragma unroll
            for (int i = 0; i < 8; i++)
#pragma unroll
                for (int j = 0; j < 8; j++)
                    acc[i][j] = fmaf(a[i], bv[j], acc[i][j]);
        }
        __syncthreads();
    }

#pragma unroll
    for (int i = 0; i < 8; i++) {
        size_t row = (size_t)(m0 + tm + i) * N + n0 + tn;
        float out[8];
#pragma unroll
        for (int j = 0; j < 8; j++) {
            float v = acc[i][j];
            if (ACT >= 1) v += bias[n0 + tn + j];
            if (ACT == 2) v = v * (1.0f / 1.1f) / (1.0f + expf(-v));
            out[j] = v;
        }
        *(float4*)(C + row)     = *(float4*)&out[0];
        *(float4*)(C + row + 4) = *(float4*)&out[4];
    }
}

// ---------------- elementwise helpers ---------------------------------------
__global__ void ew_scale(const float* __restrict__ in, float* __restrict__ out,
                         float s, int n)
{
    int i = blockIdx.x * blockDim.x + threadIdx.x;
    if (i < n) out[i] = in[i] * s;
}

// Z = cd*I + cy*Y
__global__ void ew_diag2(const float* __restrict__ Y, float* __restrict__ Z,
                         float cd, float cy, int n)
{
    int i = blockIdx.x * blockDim.x + threadIdx.x;
    if (i < n) {
        float v = cy * Y[i];
        if (((i % DD) % (D + 1)) == 0) v += cd;
        Z[i] = v;
    }
}

// Z = cd*I + cy*Y + cy2*Y2
__global__ void ew_diag3(const float* __restrict__ Y, const float* __restrict__ Y2,
                         float* __restrict__ Z, float cd, float cy, float cy2, int n)
{
    int i = blockIdx.x * blockDim.x + threadIdx.x;
    if (i < n) {
        float v = cy * Y[i] + cy2 * Y2[i];
        if (((i % DD) % (D + 1)) == 0) v += cd;
        Z[i] = v;
    }
}

// O = ca*A + cb*B
__global__ void ew_lin2(const float* __restrict__ A, const float* __restrict__ B,
                        float* __restrict__ O, float ca, float cb, int n)
{
    int i = blockIdx.x * blockDim.x + threadIdx.x;
    if (i < n) O[i] = ca * A[i] + cb * B[i];
}

// K = 0.5*(W + 0.9*P - T)
__global__ void ew_k(const float* __restrict__ W, const float* __restrict__ P,
                     const float* __restrict__ T, float* __restrict__ Kk, int n)
{
    int i = blockIdx.x * blockDim.x + threadIdx.x;
    if (i < n) Kk[i] = 0.5f * (W[i] + 0.9f * P[i] - T[i]);
}

// ---------------- launcher ---------------------------------------------------
extern "C" void kernel_launch(void* const* d_in, const int* in_sizes, int n_in,
                              void* d_out, int out_size)
{
    const float* x       = (const float*)d_in[0];
    const float* w[3]    = {(const float*)d_in[1], (const float*)d_in[3], (const float*)d_in[5]};
    const float* bias[3] = {(const float*)d_in[2], (const float*)d_in[4], (const float*)d_in[6]};

    float *W, *X, *Xb, *Q, *Qb, *Y, *Y2, *Z, *Kk, *A1, *A2;
    cudaGetSymbolAddress((void**)&W,  g_W);
    cudaGetSymbolAddress((void**)&X,  g_X);
    cudaGetSymbolAddress((void**)&Xb, g_Xb);
    cudaGetSymbolAddress((void**)&Q,  g_Q);
    cudaGetSymbolAddress((void**)&Qb, g_Qb);
    cudaGetSymbolAddress((void**)&Y,  g_Y);
    cudaGetSymbolAddress((void**)&Y2, g_Y2);
    cudaGetSymbolAddress((void**)&Z,  g_Z);
    cudaGetSymbolAddress((void**)&Kk, g_K);
    cudaGetSymbolAddress((void**)&A1, g_A1);
    cudaGetSymbolAddress((void**)&A2, g_A2);

    // pack the three weights contiguously for batched matmuls
    for (int i = 0; i < 3; i++)
        cudaMemcpyAsync(W + (size_t)i * DD, w[i], (size_t)DD * sizeof(float),
                        cudaMemcpyDeviceToDevice);

    const int EWT = 256;
    const int ewn = NB * DD;
    const int ewg = (ewn + EWT - 1) / EWT;

    dim3 blk(256);
    dim3 gW(8, 8, 3);     // 1024x1024, batch 3
    dim3 gX(8, 128, 1);   // 16384x1024

    const float q5a = 3.4445f, q5b = -4.7750f, q5c = 2.0315f; // Muon quintic
    const float aClip = 0.9f;

    // X0 = W / 2.2   (sigma_max ~= 2.0 for this Glorot matrix; safe bound)
    ew_scale<<<ewg, EWT>>>(W, X, 1.0f / 2.2f, ewn);

    // -------- P = msign(W): 6 quintic + 4 quadratic-polish NS iterations ----
    float *cur = X, *nxt = Xb;
    for (int it = 0; it < 6; it++) {
        mm_kernel<true,  0><<<gW, blk>>>(cur, cur, Y,  nullptr, D, D, D); // Y = X^T X
        mm_kernel<false, 0><<<gW, blk>>>(Y,   Y,   Y2, nullptr, D, D, D); // Y2 = Y*Y
        ew_diag3<<<ewg, EWT>>>(Y, Y2, Z, q5a, q5b, q5c, ewn);             // Z = aI+bY+cY2
        mm_kernel<false, 0><<<gW, blk>>>(cur, Z, nxt, nullptr, D, D, D);  // X = X*Z
        float* t = cur; cur = nxt; nxt = t;
    }
    for (int it = 0; it < 4; it++) {
        mm_kernel<true,  0><<<gW, blk>>>(cur, cur, Y, nullptr, D, D, D);
        ew_diag2<<<ewg, EWT>>>(Y, Z, 1.5f, -0.5f, ewn);
        mm_kernel<false, 0><<<gW, blk>>>(cur, Z, nxt, nullptr, D, D, D);
        float* t = cur; cur = nxt; nxt = t;
    }
    float* P     = cur;
    float* Mfree = nxt;   // the other ping-pong buffer is now free

    // -------- B = (P^T W - 0.9 I) / 1.15 ; Q = sign(B) -----------------------
    mm_kernel<true, 0><<<gW, blk>>>(P, W, Y, nullptr, D, D, D);           // Y = P^T W
    ew_diag2<<<ewg, EWT>>>(Y, Q, -aClip / 1.15f, 1.0f / 1.15f, ewn);

    float *qc = Q, *qn = Qb;
    for (int it = 0; it < 8; it++) {
        mm_kernel<false, 0><<<gW, blk>>>(qc, qc, Y,  nullptr, D, D, D);   // Y = Q^2
        mm_kernel<false, 0><<<gW, blk>>>(Y,  Y,  Y2, nullptr, D, D, D);   // Y2 = Q^4
        ew_diag3<<<ewg, EWT>>>(Y, Y2, Z, q5a, q5b, q5c, ewn);
        mm_kernel<false, 0><<<gW, blk>>>(qc, Z, qn, nullptr, D, D, D);
        float* t = qc; qc = qn; qn = t;
    }
    for (int it = 0; it < 4; it++) {
        mm_kernel<false, 0><<<gW, blk>>>(qc, qc, Y, nullptr, D, D, D);
        ew_diag2<<<ewg, EWT>>>(Y, Z, 1.5f, -0.5f, ewn);
        mm_kernel<false, 0><<<gW, blk>>>(qc, Z, qn, nullptr, D, D, D);
        float* t = qc; qc = qn; qn = t;
    }
    float* Qf = qc;

    // -------- clipped kernel: K = 0.5*(W + 0.9P - (W - 0.9P) Q) --------------
    ew_lin2<<<ewg, EWT>>>(W, P, Mfree, 1.0f, -aClip, ewn);                // M = W-0.9P
    mm_kernel<false, 0><<<gW, blk>>>(Mfree, Qf, Y, nullptr, D, D, D);     // T = M*Q
    ew_k<<<ewg, EWT>>>(W, P, Y, Kk, ewn);

    // -------- activation chain ----------------------------------------------
    mm_kernel<false, 2><<<gX, blk>>>(x,  Kk,          A1, bias[0], BSZ, D, D);
    mm_kernel<false, 2><<<gX, blk>>>(A1, Kk + DD,     A2, bias[1], BSZ, D, D);
    mm_kernel<false, 1><<<gX, blk>>>(A2, Kk + 2 * DD, (float*)d_out, bias[2], BSZ, D, D);
}

// round 3
// speedup vs baseline: 1.0667x; 1.0667x over previous
#include <cuda_runtime.h>
#include <math.h>
#include <stdint.h>

// Problem sizes (fixed by the reference)
#define D   1024
#define DD  (D*D)
#define NB  3
#define BSZ 16384

// ---------------- scratch (device globals; no allocations allowed) ----------
__device__ float g_W [NB*DD];
__device__ float g_X [NB*DD];
__device__ float g_Xb[NB*DD];
__device__ float g_Q [NB*DD];
__device__ float g_Qb[NB*DD];
__device__ float g_Y [NB*DD];
__device__ float g_Z [NB*DD];
__device__ float g_K [NB*DD];
__device__ float g_A1[(size_t)BSZ*D];
__device__ float g_A2[(size_t)BSZ*D];

// ---------------- pipelined tiled fp32 matmul with fused epilogues ----------
// C = epi( op(A)*B )  tile: TM x 128, 256 threads, reg-prefetch pipeline.
// TRA: op(A)=A^T (A stored physically K x M row-major); else A is M x K.
// EPI: 0 = c1*acc + cd*I
//      1 = c1*acc + c2*aux1 + cd*I            (quintic Z from Y,Y^2)
//      2 = 0.5*aux1 + 0.45*aux2 - 0.5*acc     (K-combine)
//      3 = acc + bias(aux1)                   (identity layer)
//      4 = lipswish(acc + bias(aux1))
template<bool TRA, int TM, int EPI>
__global__ void __launch_bounds__(256, 2)
mm(const float* __restrict__ A, const float* __restrict__ B,
   float* __restrict__ C,
   const float* __restrict__ aux1, const float* __restrict__ aux2,
   float cd, float c1, float c2,
   int M, int N, int K)
{
    constexpr int RT  = TM / 16;             // rows per thread
    constexpr int ALD = TM * 16 / (256 * 4); // float4 A-loads per thread

    __shared__ float As[16][TM];
    __shared__ float Bs[16][128];

    const int b = blockIdx.z;
    A += (size_t)b * M * K;
    B += (size_t)b * K * N;
    C += (size_t)b * M * N;
    if (EPI == 1 || EPI == 2) {
        aux1 += (size_t)b * M * N;
        if (EPI == 2) aux2 += (size_t)b * M * N;
    }

    const int m0  = blockIdx.y * TM;
    const int n0  = blockIdx.x * 128;
    const int tid = threadIdx.x;
    const int tm  = (tid >> 4) * RT;
    const int tn  = (tid & 15) * 8;

    float4 pa[ALD], pb[2];

    auto loadA = [&](int k0) {
#pragma unroll
        for (int i = 0; i < ALD; i++) {
            int t = tid + i * 256;
            if (TRA) {
                int kk  = (TM == 128) ? (t >> 5) : (t >> 4);
                int mmi = (TM == 128) ? ((t & 31) << 2) : ((t & 15) << 2);
                pa[i] = *(const float4*)(A + (size_t)(k0 + kk) * M + m0 + mmi);
            } else {
                int mmi = t >> 2, kk = (t & 3) << 2;
                pa[i] = *(const float4*)(A + (size_t)(m0 + mmi) * K + k0 + kk);
            }
        }
    };
    auto storeA = [&]() {
#pragma unroll
        for (int i = 0; i < ALD; i++) {
            int t = tid + i * 256;
            if (TRA) {
                int kk  = (TM == 128) ? (t >> 5) : (t >> 4);
                int mmi = (TM == 128) ? ((t & 31) << 2) : ((t & 15) << 2);
                *(float4*)&As[kk][mmi] = pa[i];
            } else {
                int mmi = t >> 2, kk = (t & 3) << 2;
                As[kk + 0][mmi] = pa[i].x;
                As[kk + 1][mmi] = pa[i].y;
                As[kk + 2][mmi] = pa[i].z;
                As[kk + 3][mmi] = pa[i].w;
            }
        }
    };
    auto loadB = [&](int k0) {
#pragma unroll
        for (int i = 0; i < 2; i++) {
            int t = tid + i * 256;
            int kk = t >> 5, nn = (t & 31) << 2;
            pb[i] = *(const float4*)(B + (size_t)(k0 + kk) * N + n0 + nn);
        }
    };
    auto storeB = [&]() {
#pragma unroll
        for (int i = 0; i < 2; i++) {
            int t = tid + i * 256;
            int kk = t >> 5, nn = (t & 31) << 2;
            *(float4*)&Bs[kk][nn] = pb[i];
        }
    };

    float acc[RT][8];
#pragma unroll
    for (int i = 0; i < RT; i++)
#pragma unroll
        for (int j = 0; j < 8; j++) acc[i][j] = 0.0f;

    const int NK = K >> 4;
    loadA(0); loadB(0);

    for (int kt = 0; kt < NK; kt++) {
        storeA(); storeB();
        __syncthreads();
        if (kt + 1 < NK) { loadA((kt + 1) << 4); loadB((kt + 1) << 4); }

#pragma unroll
        for (int kk = 0; kk < 16; kk++) {
            float a[RT], bv[8];
#pragma unroll
            for (int r = 0; r < RT; r += 4)
                *(float4*)&a[r] = *(const float4*)&As[kk][tm + r];
            *(float4*)&bv[0] = *(const float4*)&Bs[kk][tn];
            *(float4*)&bv[4] = *(const float4*)&Bs[kk][tn + 4];
#pragma unroll
            for (int i = 0; i < RT; i++)
#pragma unroll
                for (int j = 0; j < 8; j++)
                    acc[i][j] = fmaf(a[i], bv[j], acc[i][j]);
        }
        __syncthreads();
    }

#pragma unroll
    for (int i = 0; i < RT; i++) {
        const int row = m0 + tm + i;
        size_t base = (size_t)row * N + n0 + tn;
        float out[8];
#pragma unroll
        for (int j = 0; j < 8; j++) {
            const int col = n0 + tn + j;
            float v = acc[i][j];
            if (EPI == 0) {
                v = c1 * v;
                if (row == col) v += cd;
            } else if (EPI == 1) {
                v = c1 * v + c2 * aux1[base + j];
                if (row == col) v += cd;
            } else if (EPI == 2) {
                v = 0.5f * aux1[base + j] + 0.45f * aux2[base + j] - 0.5f * v;
            } else if (EPI == 3) {
                v = v + aux1[col];
            } else { // EPI == 4: lipswish
                v = v + aux1[col];
                float e = __expf(-v);
                v = __fdividef(v * (1.0f / 1.1f), 1.0f + e);
            }
            out[j] = v;
        }
        *(float4*)(C + base)     = *(float4*)&out[0];
        *(float4*)(C + base + 4) = *(float4*)&out[4];
    }
}

// ---------------- elementwise: O = ca*A + cb*B -------------------------------
__global__ void ew_lin2(const float* __restrict__ A, const float* __restrict__ B,
                        float* __restrict__ O, float ca, float cb, int n)
{
    int i = blockIdx.x * blockDim.x + threadIdx.x;
    if (i < n) O[i] = ca * A[i] + cb * B[i];
}

// ---------------- launcher ----------------------------------------------------
extern "C" void kernel_launch(void* const* d_in, const int* in_sizes, int n_in,
                              void* d_out, int out_size)
{
    const float* x       = (const float*)d_in[0];
    const float* w[3]    = {(const float*)d_in[1], (const float*)d_in[3], (const float*)d_in[5]};
    const float* bias[3] = {(const float*)d_in[2], (const float*)d_in[4], (const float*)d_in[6]};

    float *W, *X, *Xb, *Q, *Qb, *Y, *Z, *Kk, *A1, *A2;
    cudaGetSymbolAddress((void**)&W,  g_W);
    cudaGetSymbolAddress((void**)&X,  g_X);
    cudaGetSymbolAddress((void**)&Xb, g_Xb);
    cudaGetSymbolAddress((void**)&Q,  g_Q);
    cudaGetSymbolAddress((void**)&Qb, g_Qb);
    cudaGetSymbolAddress((void**)&Y,  g_Y);
    cudaGetSymbolAddress((void**)&Z,  g_Z);
    cudaGetSymbolAddress((void**)&Kk, g_K);
    cudaGetSymbolAddress((void**)&A1, g_A1);
    cudaGetSymbolAddress((void**)&A2, g_A2);

    // pack the three weights contiguously for batched matmuls
    for (int i = 0; i < 3; i++)
        cudaMemcpyAsync(W + (size_t)i * DD, w[i], (size_t)DD * sizeof(float),
                        cudaMemcpyDeviceToDevice);

    dim3 blk(256);
    dim3 gW(8, 16, 3);    // 64x128 tiles over 1024x1024, batch 3 -> 384 CTAs
    dim3 gX(8, 128, 1);   // 128x128 tiles over 16384x1024

    const float q5a = 3.4445f, q5b = -4.7750f, q5c = 2.0315f; // Muon quintic
    const float s0 = 1.0f / 2.2f;  // sigma_max(W) ~= 2.0; safe init scale
    const float NUL = 0.0f;

    // -------- P = msign(W): 5 quintic + 4 NS polish --------------------------
    // Iter 0 folds the init scaling into the matmuls (no ew_scale pass).
    mm<true,  64, 0><<<gW, blk>>>(W, W, Y, nullptr, nullptr, NUL, s0 * s0, NUL, D, D, D);
    mm<false, 64, 1><<<gW, blk>>>(Y, Y, Z, Y, nullptr, q5a, q5c, q5b, D, D, D);
    mm<false, 64, 0><<<gW, blk>>>(W, Z, X, nullptr, nullptr, NUL, s0, NUL, D, D, D);

    float *cur = X, *nxt = Xb;
    for (int it = 0; it < 4; it++) {             // 4 more quintics (5 total)
        mm<true,  64, 0><<<gW, blk>>>(cur, cur, Y, nullptr, nullptr, NUL, 1.0f, NUL, D, D, D);
        mm<false, 64, 1><<<gW, blk>>>(Y, Y, Z, Y, nullptr, q5a, q5c, q5b, D, D, D);
        mm<false, 64, 0><<<gW, blk>>>(cur, Z, nxt, nullptr, nullptr, NUL, 1.0f, NUL, D, D, D);
        float* t = cur; cur = nxt; nxt = t;
    }
    for (int it = 0; it < 4; it++) {             // NS quadratic polish
        mm<true,  64, 0><<<gW, blk>>>(cur, cur, Z, nullptr, nullptr, 1.5f, -0.5f, NUL, D, D, D);
        mm<false, 64, 0><<<gW, blk>>>(cur, Z, nxt, nullptr, nullptr, NUL, 1.0f, NUL, D, D, D);
        float* t = cur; cur = nxt; nxt = t;
    }
    float* P     = cur;
    float* Mbuf  = nxt;    // free ping-pong buffer

    // -------- Q = sign((P^T W - 0.9 I)/1.15): 6 quintic + 4 NS ---------------
    mm<true, 64, 0><<<gW, blk>>>(P, W, Q, nullptr, nullptr, -0.9f / 1.15f, 1.0f / 1.15f, NUL, D, D, D);

    float *qc = Q, *qn = Qb;
    for (int it = 0; it < 6; it++) {
        mm<false, 64, 0><<<gW, blk>>>(qc, qc, Y, nullptr, nullptr, NUL, 1.0f, NUL, D, D, D);
        mm<false, 64, 1><<<gW, blk>>>(Y, Y, Z, Y, nullptr, q5a, q5c, q5b, D, D, D);
        mm<false, 64, 0><<<gW, blk>>>(qc, Z, qn, nullptr, nullptr, NUL, 1.0f, NUL, D, D, D);
        float* t = qc; qc = qn; qn = t;
    }
    for (int it = 0; it < 4; it++) {
        mm<false, 64, 0><<<gW, blk>>>(qc, qc, Z, nullptr, nullptr, 1.5f, -0.5f, NUL, D, D, D);
        mm<false, 64, 0><<<gW, blk>>>(qc, Z, qn, nullptr, nullptr, NUL, 1.0f, NUL, D, D, D);
        float* t = qc; qc = qn; qn = t;
    }
    float* Qf = qc;
    if (qn != Mbuf && Qf != Mbuf) { /* Mbuf stays valid */ }
    if (Qf == Mbuf) Mbuf = qn;     // safety: never collide (can't happen, but cheap)

    // -------- clipped kernel: K = 0.5*(W + 0.9P - (W - 0.9P) Q) --------------
    {
        const int EWT = 256, ewn = NB * DD, ewg = (ewn + EWT - 1) / EWT;
        ew_lin2<<<ewg, EWT>>>(W, P, Mbuf, 1.0f, -0.9f, ewn);               // M = W - 0.9P
    }
    mm<false, 64, 2><<<gW, blk>>>(Mbuf, Qf, Kk, W, P, NUL, NUL, NUL, D, D, D);

    // -------- activation chain ------------------------------------------------
    mm<false, 128, 4><<<gX, blk>>>(x,  Kk,          A1, bias[0], nullptr, NUL, NUL, NUL, BSZ, D, D);
    mm<false, 128, 4><<<gX, blk>>>(A1, Kk + DD,     A2, bias[1], nullptr, NUL, NUL, NUL, BSZ, D, D);
    mm<false, 128, 3><<<gX, blk>>>(A2, Kk + 2 * DD, (float*)d_out, bias[2], nullptr, NUL, NUL, NUL, BSZ, D, D);
}

// round 4
// speedup vs baseline: 1.0674x; 1.0006x over previous
#include <cuda_runtime.h>
#include <math.h>
#include <stdint.h>

// Problem sizes (fixed by the reference)
#define D   1024
#define DD  (D*D)
#define NB  3
#define BSZ 16384

// ---------------- scratch (device globals; no allocations allowed) ----------
__device__ float g_W [NB*DD];
__device__ float g_X [NB*DD];
__device__ float g_Xb[NB*DD];
__device__ float g_Q [NB*DD];
__device__ float g_Qb[NB*DD];
__device__ float g_Y [NB*DD];
__device__ float g_Z [NB*DD];
__device__ float g_K [NB*DD];
__device__ float g_A1[(size_t)BSZ*D];
__device__ float g_A2[(size_t)BSZ*D];

// ---------------- pipelined tiled fp32 matmul with fused epilogues ----------
// C = epi( op(A)*B )  tile: TM x 128, 256 threads, reg-prefetch pipeline.
// TRA: op(A)=A^T (A stored physically K x M row-major); else A is M x K.
// EPI: 0 = c1*acc + cd*I
//      1 = c1*acc + c2*aux1 + cd*I            (quintic Z from Y,Y^2)
//      2 = 0.5*aux1 + 0.45*aux2 - 0.5*acc     (K-combine)
//      3 = acc + bias(aux1)                   (identity layer)
//      4 = lipswish(acc + bias(aux1))
template<bool TRA, int TM, int EPI>
__global__ void __launch_bounds__(256, 2)
mm(const float* __restrict__ A, const float* __restrict__ B,
   float* __restrict__ C,
   const float* __restrict__ aux1, const float* __restrict__ aux2,
   float cd, float c1, float c2,
   int M, int N, int K)
{
    constexpr int RT  = TM / 16;             // rows per thread
    constexpr int ALD = TM * 16 / (256 * 4); // float4 A-loads per thread

    __shared__ float As[16][TM];
    __shared__ float Bs[16][128];

    const int b = blockIdx.z;
    A += (size_t)b * M * K;
    B += (size_t)b * K * N;
    C += (size_t)b * M * N;
    if (EPI == 1 || EPI == 2) {
        aux1 += (size_t)b * M * N;
        if (EPI == 2) aux2 += (size_t)b * M * N;
    }

    const int m0  = blockIdx.y * TM;
    const int n0  = blockIdx.x * 128;
    const int tid = threadIdx.x;
    const int tm  = (tid >> 4) * RT;
    const int tn  = (tid & 15) * 8;

    float4 pa[ALD], pb[2];

    auto loadA = [&](int k0) {
#pragma unroll
        for (int i = 0; i < ALD; i++) {
            int t = tid + i * 256;
            if (TRA) {
                int kk  = (TM == 128) ? (t >> 5) : (t >> 4);
                int mmi = (TM == 128) ? ((t & 31) << 2) : ((t & 15) << 2);
                pa[i] = *(const float4*)(A + (size_t)(k0 + kk) * M + m0 + mmi);
            } else {
                int mmi = t >> 2, kk = (t & 3) << 2;
                pa[i] = *(const float4*)(A + (size_t)(m0 + mmi) * K + k0 + kk);
            }
        }
    };
    auto storeA = [&]() {
#pragma unroll
        for (int i = 0; i < ALD; i++) {
            int t = tid + i * 256;
            if (TRA) {
                int kk  = (TM == 128) ? (t >> 5) : (t >> 4);
                int mmi = (TM == 128) ? ((t & 31) << 2) : ((t & 15) << 2);
                *(float4*)&As[kk][mmi] = pa[i];
            } else {
                int mmi = t >> 2, kk = (t & 3) << 2;
                As[kk + 0][mmi] = pa[i].x;
                As[kk + 1][mmi] = pa[i].y;
                As[kk + 2][mmi] = pa[i].z;
                As[kk + 3][mmi] = pa[i].w;
            }
        }
    };
    auto loadB = [&](int k0) {
#pragma unroll
        for (int i = 0; i < 2; i++) {
            int t = tid + i * 256;
            int kk = t >> 5, nn = (t & 31) << 2;
            pb[i] = *(const float4*)(B + (size_t)(k0 + kk) * N + n0 + nn);
        }
    };
    auto storeB = [&]() {
#pragma unroll
        for (int i = 0; i < 2; i++) {
            int t = tid + i * 256;
            int kk = t >> 5, nn = (t & 31) << 2;
            *(float4*)&Bs[kk][nn] = pb[i];
        }
    };

    float acc[RT][8];
#pragma unroll
    for (int i = 0; i < RT; i++)
#pragma unroll
        for (int j = 0; j < 8; j++) acc[i][j] = 0.0f;

    const int NK = K >> 4;
    loadA(0); loadB(0);

    for (int kt = 0; kt < NK; kt++) {
        storeA(); storeB();
        __syncthreads();
        if (kt + 1 < NK) { loadA((kt + 1) << 4); loadB((kt + 1) << 4); }

#pragma unroll
        for (int kk = 0; kk < 16; kk++) {
            float a[RT], bv[8];
#pragma unroll
            for (int r = 0; r < RT; r += 4)
                *(float4*)&a[r] = *(const float4*)&As[kk][tm + r];
            *(float4*)&bv[0] = *(const float4*)&Bs[kk][tn];
            *(float4*)&bv[4] = *(const float4*)&Bs[kk][tn + 4];
#pragma unroll
            for (int i = 0; i < RT; i++)
#pragma unroll
                for (int j = 0; j < 8; j++)
                    acc[i][j] = fmaf(a[i], bv[j], acc[i][j]);
        }
        __syncthreads();
    }

#pragma unroll
    for (int i = 0; i < RT; i++) {
        const int row = m0 + tm + i;
        size_t base = (size_t)row * N + n0 + tn;
        float out[8];
#pragma unroll
        for (int j = 0; j < 8; j++) {
            const int col = n0 + tn + j;
            float v = acc[i][j];
            if (EPI == 0) {
                v = c1 * v;
                if (row == col) v += cd;
            } else if (EPI == 1) {
                v = c1 * v + c2 * aux1[base + j];
                if (row == col) v += cd;
            } else if (EPI == 2) {
                v = 0.5f * aux1[base + j] + 0.45f * aux2[base + j] - 0.5f * v;
            } else if (EPI == 3) {
                v = v + aux1[col];
            } else { // EPI == 4: lipswish
                v = v + aux1[col];
                float e = __expf(-v);
                v = __fdividef(v * (1.0f / 1.1f), 1.0f + e);
            }
            out[j] = v;
        }
        *(float4*)(C + base)     = *(float4*)&out[0];
        *(float4*)(C + base + 4) = *(float4*)&out[4];
    }
}

// ---------------- elementwise: O = ca*A + cb*B -------------------------------
__global__ void ew_lin2(const float* __restrict__ A, const float* __restrict__ B,
                        float* __restrict__ O, float ca, float cb, int n)
{
    int i = blockIdx.x * blockDim.x + threadIdx.x;
    if (i < n) O[i] = ca * A[i] + cb * B[i];
}

// ---------------- launcher ----------------------------------------------------
extern "C" void kernel_launch(void* const* d_in, const int* in_sizes, int n_in,
                              void* d_out, int out_size)
{
    const float* x       = (const float*)d_in[0];
    const float* w[3]    = {(const float*)d_in[1], (const float*)d_in[3], (const float*)d_in[5]};
    const float* bias[3] = {(const float*)d_in[2], (const float*)d_in[4], (const float*)d_in[6]};

    float *W, *X, *Xb, *Q, *Qb, *Y, *Z, *Kk, *A1, *A2;
    cudaGetSymbolAddress((void**)&W,  g_W);
    cudaGetSymbolAddress((void**)&X,  g_X);
    cudaGetSymbolAddress((void**)&Xb, g_Xb);
    cudaGetSymbolAddress((void**)&Q,  g_Q);
    cudaGetSymbolAddress((void**)&Qb, g_Qb);
    cudaGetSymbolAddress((void**)&Y,  g_Y);
    cudaGetSymbolAddress((void**)&Z,  g_Z);
    cudaGetSymbolAddress((void**)&Kk, g_K);
    cudaGetSymbolAddress((void**)&A1, g_A1);
    cudaGetSymbolAddress((void**)&A2, g_A2);

    // pack the three weights contiguously for batched matmuls
    for (int i = 0; i < 3; i++)
        cudaMemcpyAsync(W + (size_t)i * DD, w[i], (size_t)DD * sizeof(float),
                        cudaMemcpyDeviceToDevice);

    dim3 blk(256);
    dim3 gW(8, 16, 3);    // 64x128 tiles over 1024x1024, batch 3 -> 384 CTAs
    dim3 gX(8, 128, 1);   // 128x128 tiles over 16384x1024

    const float q5a = 3.4445f, q5b = -4.7750f, q5c = 2.0315f; // Muon quintic
    const float s0 = 1.0f / 2.2f;  // sigma_max(W) ~= 2.0; safe init scale
    const float NUL = 0.0f;

    // -------- P = msign(W): 5 quintic + 4 NS polish --------------------------
    // Iter 0 folds the init scaling into the matmuls (no ew_scale pass).
    mm<true,  64, 0><<<gW, blk>>>(W, W, Y, nullptr, nullptr, NUL, s0 * s0, NUL, D, D, D);
    mm<false, 64, 1><<<gW, blk>>>(Y, Y, Z, Y, nullptr, q5a, q5c, q5b, D, D, D);
    mm<false, 64, 0><<<gW, blk>>>(W, Z, X, nullptr, nullptr, NUL, s0, NUL, D, D, D);

    float *cur = X, *nxt = Xb;
    for (int it = 0; it < 4; it++) {             // 4 more quintics (5 total)
        mm<true,  64, 0><<<gW, blk>>>(cur, cur, Y, nullptr, nullptr, NUL, 1.0f, NUL, D, D, D);
        mm<false, 64, 1><<<gW, blk>>>(Y, Y, Z, Y, nullptr, q5a, q5c, q5b, D, D, D);
        mm<false, 64, 0><<<gW, blk>>>(cur, Z, nxt, nullptr, nullptr, NUL, 1.0f, NUL, D, D, D);
        float* t = cur; cur = nxt; nxt = t;
    }
    for (int it = 0; it < 4; it++) {             // NS quadratic polish
        mm<true,  64, 0><<<gW, blk>>>(cur, cur, Z, nullptr, nullptr, 1.5f, -0.5f, NUL, D, D, D);
        mm<false, 64, 0><<<gW, blk>>>(cur, Z, nxt, nullptr, nullptr, NUL, 1.0f, NUL, D, D, D);
        float* t = cur; cur = nxt; nxt = t;
    }
    float* P     = cur;
    float* Mbuf  = nxt;    // free ping-pong buffer

    // -------- Q = sign((P^T W - 0.9 I)/1.15): 6 quintic + 4 NS ---------------
    mm<true, 64, 0><<<gW, blk>>>(P, W, Q, nullptr, nullptr, -0.9f / 1.15f, 1.0f / 1.15f, NUL, D, D, D);

    float *qc = Q, *qn = Qb;
    for (int it = 0; it < 6; it++) {
        mm<false, 64, 0><<<gW, blk>>>(qc, qc, Y, nullptr, nullptr, NUL, 1.0f, NUL, D, D, D);
        mm<false, 64, 1><<<gW, blk>>>(Y, Y, Z, Y, nullptr, q5a, q5c, q5b, D, D, D);
        mm<false, 64, 0><<<gW, blk>>>(qc, Z, qn, nullptr, nullptr, NUL, 1.0f, NUL, D, D, D);
        float* t = qc; qc = qn; qn = t;
    }
    for (int it = 0; it < 4; it++) {
        mm<false, 64, 0><<<gW, blk>>>(qc, qc, Z, nullptr, nullptr, 1.5f, -0.5f, NUL, D, D, D);
        mm<false, 64, 0><<<gW, blk>>>(qc, Z, qn, nullptr, nullptr, NUL, 1.0f, NUL, D, D, D);
        float* t = qc; qc = qn; qn = t;
    }
    float* Qf = qc;
    if (qn != Mbuf && Qf != Mbuf) { /* Mbuf stays valid */ }
    if (Qf == Mbuf) Mbuf = qn;     // safety: never collide (can't happen, but cheap)

    // -------- clipped kernel: K = 0.5*(W + 0.9P - (W - 0.9P) Q) --------------
    {
        const int EWT = 256, ewn = NB * DD, ewg = (ewn + EWT - 1) / EWT;
        ew_lin2<<<ewg, EWT>>>(W, P, Mbuf, 1.0f, -0.9f, ewn);               // M = W - 0.9P
    }
    mm<false, 64, 2><<<gW, blk>>>(Mbuf, Qf, Kk, W, P, NUL, NUL, NUL, D, D, D);

    // -------- activation chain ------------------------------------------------
    mm<false, 128, 4><<<gX, blk>>>(x,  Kk,          A1, bias[0], nullptr, NUL, NUL, NUL, BSZ, D, D);
    mm<false, 128, 4><<<gX, blk>>>(A1, Kk + DD,     A2, bias[1], nullptr, NUL, NUL, NUL, BSZ, D, D);
    mm<false, 128, 3><<<gX, blk>>>(A2, Kk + 2 * DD, (float*)d_out, bias[2], nullptr, NUL, NUL, NUL, BSZ, D, D);
}